// round 15
// baseline (speedup 1.0000x reference)
#include <cuda_runtime.h>

// ---------------------------------------------------------------------------
// Problem constants (IN = OUT = 4096, batch M = 512)
// ---------------------------------------------------------------------------
#define NP 4096
#define KTOP 3687.0f
#define INV_LR 100.0f
#define NUM_ITER 50

__device__ float g_W[(size_t)4096 * 4096];       // tf32-rounded W
__device__ float g_xr[(size_t)512 * 4096];       // tf32-rounded x
__device__ float g_D;                            // converged dykstra shift
__device__ int   g_flag;                         // g_D published (sticky across replays; benign)

// ---------------------------------------------------------------------------
// Helpers
// ---------------------------------------------------------------------------
__device__ __forceinline__ unsigned f2tf32(float f) {
    unsigned u;
    asm("cvt.rna.tf32.f32 %0, %1;" : "=r"(u) : "f"(f));
    return u;
}
__device__ __forceinline__ void cp_async16(unsigned dst, const void* src) {
    asm volatile("cp.async.cg.shared.global [%0], [%1], 16;" :: "r"(dst), "l"(src));
}
__device__ __forceinline__ unsigned smem_u32(const void* p) {
    unsigned a;
    asm("{ .reg .u64 t; cvta.to.shared.u64 t, %1; cvt.u32.u64 %0, t; }" : "=r"(a) : "l"(p));
    return a;
}
__device__ __forceinline__ int redux_add(int v) {
    int r;
    asm volatile("redux.sync.add.s32 %0, %1, 0xffffffff;" : "=r"(r) : "r"(v));
    return r;
}
__device__ __forceinline__ void mma_tf32(float* d, const unsigned* a, const unsigned* b) {
    asm volatile("mma.sync.aligned.m16n8k8.row.col.f32.tf32.tf32.f32 "
                 "{%0,%1,%2,%3}, {%4,%5,%6,%7}, {%8,%9}, {%0,%1,%2,%3};"
                 : "+f"(d[0]), "+f"(d[1]), "+f"(d[2]), "+f"(d[3])
                 : "r"(a[0]), "r"(a[1]), "r"(a[2]), "r"(a[3]), "r"(b[0]), "r"(b[1]));
}
__device__ __forceinline__ void ldsm4(unsigned* d, unsigned addr) {
    asm volatile("ldmatrix.sync.aligned.m8n8.x4.shared.b16 {%0,%1,%2,%3}, [%4];"
                 : "=r"(d[0]), "=r"(d[1]), "=r"(d[2]), "=r"(d[3]) : "r"(addr));
}

// ---------------------------------------------------------------------------
// Kernel 1 (fused pre-GEMM):
//   block 0        : collapsed Dykstra (early exit on exact convergence),
//                    publishes scalar g_D + g_flag.
//   blocks 1..2048 : roundx (g_xr = tf32(x)), independent.
//   blocks 2049+   : build_w; spin on g_flag (block 0 is wave-1 resident ->
//                    no deadlock), mask computed inline: clip(alpha*100 + D).
//   Replay note: g_flag stays 1 and g_D holds bitwise-identical values on
//   every replay (deterministic in inputs), so stale reads are benign.
// ---------------------------------------------------------------------------
#define WB_ROWS 128
#define WB_COLS 32
#define BAND_ROWS 160
#define BSTRIDE 36
#define RX_BLOCKS 2048                       // 512*4096/4/256
#define BW_BLOCKS 4096                       // (4096/128) * (4096/32)

__global__ __launch_bounds__(256) void prep_kernel(const float* __restrict__ alpha,
                                                   const float* __restrict__ V,
                                                   const float* __restrict__ x) {
    const int tid = threadIdx.x;

    if (blockIdx.x == 0) {
        // ---- Dykstra (collapsed): D += (K - sum clip(s_i + D))/n ----
        __shared__ int ctr[NUM_ITER];
        const int lane = tid & 31;
        if (tid < NUM_ITER) ctr[tid] = 0;

        float s[16];
#pragma unroll
        for (int e = 0; e < 16; e++) s[e] = alpha[e * 256 + tid] * INV_LR;
        __syncthreads();

        float D = 0.f;
        for (int it = 0; it < NUM_ITER; it++) {
            float part = 0.f;
#pragma unroll
            for (int e = 0; e < 16; e++) part += fminf(fmaxf(s[e] + D, 0.f), 1.f);
            int p = redux_add(__float2int_rn(part * 65536.0f));
            if (lane == 0) atomicAdd(&ctr[it], p);
            __syncthreads();
            float total = (float)ctr[it] * (1.0f / 65536.0f);
            float delta = (KTOP - total) * (1.0f / (float)NP);
            if (delta == 0.0f) break;    // uniform across block (ctr is shared)
            D += delta;
        }
        if (tid == 0) {
            g_D = D;
            __threadfence();
            atomicExch(&g_flag, 1);
        }
        return;
    }

    if (blockIdx.x <= RX_BLOCKS) {
        // ---- roundx ----
        int i = (blockIdx.x - 1) * 256 + tid;
        float4 v = ((const float4*)x)[i];
        uint4 o;
        o.x = f2tf32(v.x); o.y = f2tf32(v.y); o.z = f2tf32(v.z); o.w = f2tf32(v.w);
        ((uint4*)g_xr)[i] = o;
        return;
    }

    // ---- build_w ----
    const int b = blockIdx.x - (RX_BLOCKS + 1);
    __shared__ float sV[BAND_ROWS * BSTRIDE];
    __shared__ float sD;
    const int r0 = (b >> 7) * WB_ROWS;       // 32 r-tiles
    const int j0 = (b & 127) * WB_COLS;      // 128 j-tiles
    const int i_min = (r0 - j0 - (WB_COLS - 1) + 2 * NP) & (NP - 1);

    if (tid == 0) {
        while (*(volatile int*)&g_flag == 0) __nanosleep(64);
        __threadfence();
        sD = *(volatile float*)&g_D;
    }
    __syncthreads();
    const float D = sD;

    for (int idx = tid; idx < BAND_ROWS * 8; idx += 256) {
        int t = idx >> 3, u = idx & 7;
        int gi = (i_min + t) & (NP - 1);
        float m = fminf(fmaxf(alpha[gi] * INV_LR + D, 0.f), 1.f);
        float4 v = *(const float4*)(V + (size_t)gi * 4096 + j0 + u * 4);
        float* d = &sV[t * BSTRIDE + u * 4];
        d[0] = m * v.x; d[1] = m * v.y; d[2] = m * v.z; d[3] = m * v.w;
    }
    __syncthreads();

    const int jj4 = (tid & 7) * 4;
    const int rb = tid >> 3;
#pragma unroll
    for (int i = 0; i < 4; i++) {
        int rr = rb + i * 32;
        uint4 o;
        o.x = f2tf32(sV[(rr - (jj4 + 0) + 31) * BSTRIDE + jj4 + 0]);
        o.y = f2tf32(sV[(rr - (jj4 + 1) + 31) * BSTRIDE + jj4 + 1]);
        o.z = f2tf32(sV[(rr - (jj4 + 2) + 31) * BSTRIDE + jj4 + 2]);
        o.w = f2tf32(sV[(rr - (jj4 + 3) + 31) * BSTRIDE + jj4 + 3]);
        *(uint4*)(g_W + (size_t)(r0 + rr) * 4096 + j0 + jj4) = o;
    }
}

// ---------------------------------------------------------------------------
// Kernel 2: tf32 mma.sync GEMM  C[512,4096] = g_xr * g_W^T   (R12 config)
//   BM=BN=128, BK=64 (two 32-k sub-tiles per stage), 3-stage cp.async,
//   4 warps (64x64), ldmatrix.x4 fragments, intra-chunk frag double-buffer.
// ---------------------------------------------------------------------------
#define BM 128
#define BN 128
#define BK 64
#define STAGES 3
#define NCHUNK 64
#define SUB_A 16384                          // A sub-tile bytes (128 x 32 x 4)
#define SUB_BYTES 32768                      // A sub + B sub
#define STAGE_BYTES (2 * SUB_BYTES)          // 65536
#define SMEM_TOTAL (STAGES * STAGE_BYTES)    // 196608

__global__ void __launch_bounds__(128, 1) mma_gemm_kernel(float* __restrict__ C) {
    extern __shared__ char smem[];
    const unsigned sbase = smem_u32(smem);
    const int tid = threadIdx.x;
    const int lane = tid & 31;
    const int warp = tid >> 5;
    const int m0 = blockIdx.y * BM;
    const int n0 = blockIdx.x * BN;
    const int wm = (warp & 1) * 64;
    const int wn = (warp >> 1) * 64;
    const int r = lane >> 2;
    const int c = lane & 3;
    const unsigned lane7 = lane & 7;
    const unsigned hA = lane >> 4;
    const unsigned hB = (lane >> 3) & 1;

    const float* __restrict__ Ag = g_xr + (size_t)m0 * 4096;
    const float* __restrict__ Bg = g_W + (size_t)n0 * 4096;

    unsigned aoff[4], boff[4];
#pragma unroll
    for (int mt = 0; mt < 4; mt++)
        aoff[mt] = (unsigned)((wm + mt * 16 + (lane & 15)) << 7);
#pragma unroll
    for (int np = 0; np < 4; np++)
        boff[np] = (unsigned)((wn + (2 * np + (lane >> 4)) * 8 + (lane & 7)) << 7) + SUB_A;

    float acc[4][8][4];
#pragma unroll
    for (int mt = 0; mt < 4; mt++)
#pragma unroll
        for (int nt = 0; nt < 8; nt++)
#pragma unroll
            for (int e = 0; e < 4; e++) acc[mt][nt][e] = 0.f;

    unsigned a_f[2][4][4], b_f[2][4][4];

#define LOAD_CHUNK(cc, stoff)                                                     \
    do {                                                                          \
        _Pragma("unroll")                                                         \
        for (int sub = 0; sub < 2; sub++) {                                       \
            const unsigned aB = sbase + (stoff) + sub * SUB_BYTES;                \
            const unsigned bB = aB + SUB_A;                                       \
            const int kb = (cc) * BK + sub * 32;                                  \
            _Pragma("unroll")                                                     \
            for (int i = 0; i < 8; i++) {                                         \
                int idx = tid + i * 128;                                          \
                int row = idx >> 3, u = idx & 7;                                  \
                unsigned sw = (unsigned)((row << 7) + ((u ^ (row & 7)) << 4));    \
                cp_async16(aB + sw, Ag + (size_t)row * 4096 + kb + u * 4);        \
            }                                                                     \
            _Pragma("unroll")                                                     \
            for (int i = 0; i < 8; i++) {                                         \
                int idx = tid + i * 128;                                          \
                int row = idx >> 3, u = idx & 7;                                  \
                unsigned sw = (unsigned)((row << 7) + ((u ^ (row & 7)) << 4));    \
                cp_async16(bB + sw, Bg + (size_t)row * 4096 + kb + u * 4);        \
            }                                                                     \
        }                                                                         \
    } while (0)

#define LD_FRAG(buf, stoff, ks)                                                   \
    do {                                                                          \
        const unsigned base_ = sbase + (stoff) + ((ks) >> 2) * SUB_BYTES;         \
        const unsigned ki_ = (ks) & 3;                                            \
        unsigned swA = ((2u * ki_ + hA) ^ lane7) << 4;                            \
        unsigned swB = ((2u * ki_ + hB) ^ lane7) << 4;                            \
        _Pragma("unroll")                                                         \
        for (int mt = 0; mt < 4; mt++)                                            \
            ldsm4(a_f[buf][mt], base_ + aoff[mt] + swA);                          \
        _Pragma("unroll")                                                         \
        for (int np = 0; np < 4; np++)                                            \
            ldsm4(b_f[buf][np], base_ + boff[np] + swB);                          \
    } while (0)

    LOAD_CHUNK(0, 0);
    asm volatile("cp.async.commit_group;" ::: "memory");
    LOAD_CHUNK(1, STAGE_BYTES);
    asm volatile("cp.async.commit_group;" ::: "memory");

    int st = 0;
    int lst = 2;
    for (int cc = 0; cc < NCHUNK; cc++) {
        asm volatile("cp.async.wait_group 1;" ::: "memory");
        __syncthreads();

        if (cc + 2 < NCHUNK) LOAD_CHUNK(cc + 2, lst * STAGE_BYTES);
        asm volatile("cp.async.commit_group;" ::: "memory");

        const unsigned stoff = (unsigned)(st * STAGE_BYTES);
        LD_FRAG(0, stoff, 0);

#pragma unroll
        for (int ks = 0; ks < 8; ks++) {
            const int cur = ks & 1;
            if (ks < 7) LD_FRAG(cur ^ 1, stoff, ks + 1);
#pragma unroll
            for (int mt = 0; mt < 4; mt++)
#pragma unroll
                for (int nt = 0; nt < 8; nt++)
                    mma_tf32(acc[mt][nt], a_f[cur][mt], &b_f[cur][nt >> 1][(nt & 1) * 2]);
        }

        st = (st + 1 == STAGES) ? 0 : st + 1;
        lst = (lst + 1 == STAGES) ? 0 : lst + 1;
    }

#pragma unroll
    for (int mt = 0; mt < 4; mt++) {
        int row = m0 + wm + mt * 16 + r;
#pragma unroll
        for (int nt = 0; nt < 8; nt++) {
            int col = n0 + wn + nt * 8 + 2 * c;
            *(float2*)(C + (size_t)row * 4096 + col) = make_float2(acc[mt][nt][0], acc[mt][nt][1]);
            *(float2*)(C + (size_t)(row + 8) * 4096 + col) = make_float2(acc[mt][nt][2], acc[mt][nt][3]);
        }
    }
#undef LOAD_CHUNK
#undef LD_FRAG
}

// ---------------------------------------------------------------------------
extern "C" void kernel_launch(void* const* d_in, const int* in_sizes, int n_in,
                              void* d_out, int out_size) {
    const float* x = nullptr;
    const float* V = nullptr;
    const float* alpha = nullptr;
    for (int i = 0; i < n_in; i++) {
        if (in_sizes[i] == 512 * 4096)       x     = (const float*)d_in[i];
        else if (in_sizes[i] == 4096 * 4096) V     = (const float*)d_in[i];
        else if (in_sizes[i] == 4096)        alpha = (const float*)d_in[i];
    }

    cudaFuncSetAttribute(mma_gemm_kernel, cudaFuncAttributeMaxDynamicSharedMemorySize, SMEM_TOTAL);

    prep_kernel<<<1 + RX_BLOCKS + BW_BLOCKS, 256>>>(alpha, V, x);
    mma_gemm_kernel<<<dim3(4096 / BN, 512 / BM), 128, SMEM_TOTAL>>>((float*)d_out);
}

// round 16
// speedup vs baseline: 1.5050x; 1.5050x over previous
#include <cuda_runtime.h>
#include <cuda_fp16.h>

// ---------------------------------------------------------------------------
// Problem constants (IN = OUT = 4096, batch M = 512)
// ---------------------------------------------------------------------------
#define NP 4096
#define KTOP 3687.0f
#define INV_LR 100.0f
#define NUM_ITER 50

__device__ float  g_mask[NP];
__device__ __half g_Wh[(size_t)4096 * 4096];     // fp16 W (32 MB)
__device__ __half g_xh[(size_t)512 * 4096];      // fp16 x (4 MB)

// ---------------------------------------------------------------------------
// Helpers
// ---------------------------------------------------------------------------
__device__ __forceinline__ void cp_async16(unsigned dst, const void* src) {
    asm volatile("cp.async.cg.shared.global [%0], [%1], 16;" :: "r"(dst), "l"(src));
}
__device__ __forceinline__ unsigned smem_u32(const void* p) {
    unsigned a;
    asm("{ .reg .u64 t; cvta.to.shared.u64 t, %1; cvt.u32.u64 %0, t; }" : "=r"(a) : "l"(p));
    return a;
}
__device__ __forceinline__ int redux_add(int v) {
    int r;
    asm volatile("redux.sync.add.s32 %0, %1, 0xffffffff;" : "=r"(r) : "r"(v));
    return r;
}
// fp16 tensor mma: D(f32) += A(f16) * B(f16), 16x8x16
__device__ __forceinline__ void mma_f16(float* d, const unsigned* a, const unsigned* b) {
    asm volatile("mma.sync.aligned.m16n8k16.row.col.f32.f16.f16.f32 "
                 "{%0,%1,%2,%3}, {%4,%5,%6,%7}, {%8,%9}, {%0,%1,%2,%3};"
                 : "+f"(d[0]), "+f"(d[1]), "+f"(d[2]), "+f"(d[3])
                 : "r"(a[0]), "r"(a[1]), "r"(a[2]), "r"(a[3]), "r"(b[0]), "r"(b[1]));
}
__device__ __forceinline__ void ldsm4(unsigned* d, unsigned addr) {
    asm volatile("ldmatrix.sync.aligned.m8n8.x4.shared.b16 {%0,%1,%2,%3}, [%4];"
                 : "=r"(d[0]), "=r"(d[1]), "=r"(d[2]), "=r"(d[3]) : "r"(addr));
}

// ---------------------------------------------------------------------------
// Kernel 1: collapsed Dykstra soft-top-k with exact-convergence early exit.
// ---------------------------------------------------------------------------
__global__ __launch_bounds__(256) void dykstra_kernel(const float* __restrict__ alpha) {
    __shared__ int ctr[NUM_ITER];
    const int tid = threadIdx.x, lane = tid & 31;

    if (tid < NUM_ITER) ctr[tid] = 0;

    float s[16];
#pragma unroll
    for (int e = 0; e < 16; e++) s[e] = alpha[e * 256 + tid] * INV_LR;

    __syncthreads();

    float D = 0.f;
    for (int it = 0; it < NUM_ITER; it++) {
        float part = 0.f;
#pragma unroll
        for (int e = 0; e < 16; e++) part += fminf(fmaxf(s[e] + D, 0.f), 1.f);
        int p = redux_add(__float2int_rn(part * 65536.0f));
        if (lane == 0) atomicAdd(&ctr[it], p);
        __syncthreads();
        float total = (float)ctr[it] * (1.0f / 65536.0f);
        float delta = (KTOP - total) * (1.0f / (float)NP);
        if (delta == 0.0f) break;        // uniform across block (ctr is shared)
        D += delta;
    }
#pragma unroll
    for (int e = 0; e < 16; e++)
        g_mask[e * 256 + tid] = fminf(fmaxf(s[e] + D, 0.f), 1.f);
}

// ---------------------------------------------------------------------------
// Kernel 2: fused rx (blocks 0..2047) + build_w (blocks 2048..6143), fp16 out.
//   rx: g_xh = fp16(x).   build_w: g_Wh[r][j] = fp16(mask[(r-j)&4095]*V[i][j]).
// ---------------------------------------------------------------------------
#define WB_ROWS 128
#define WB_COLS 32
#define BAND_ROWS 160
#define BSTRIDE 36
#define RX_BLOCKS 2048                       // 512*4096/4/256
#define BW_BLOCKS 4096                       // (4096/128) * (4096/32)

__global__ __launch_bounds__(256) void bw_rx_kernel(const float* __restrict__ V,
                                                    const float* __restrict__ x) {
    const int tid = threadIdx.x;
    if (blockIdx.x < RX_BLOCKS) {
        int i = blockIdx.x * 256 + tid;
        float4 v = ((const float4*)x)[i];
        __half2 h0 = __floats2half2_rn(v.x, v.y);
        __half2 h1 = __floats2half2_rn(v.z, v.w);
        uint2 o;
        o.x = *reinterpret_cast<unsigned*>(&h0);
        o.y = *reinterpret_cast<unsigned*>(&h1);
        ((uint2*)g_xh)[i] = o;
        return;
    }
    const int b = blockIdx.x - RX_BLOCKS;
    __shared__ float sV[BAND_ROWS * BSTRIDE];
    const int r0 = (b >> 7) * WB_ROWS;       // 32 r-tiles
    const int j0 = (b & 127) * WB_COLS;      // 128 j-tiles
    const int i_min = (r0 - j0 - (WB_COLS - 1) + 2 * NP) & (NP - 1);

    for (int idx = tid; idx < BAND_ROWS * 8; idx += 256) {
        int t = idx >> 3, u = idx & 7;
        int gi = (i_min + t) & (NP - 1);
        float m = g_mask[gi];
        float4 v = *(const float4*)(V + (size_t)gi * 4096 + j0 + u * 4);
        float* d = &sV[t * BSTRIDE + u * 4];
        d[0] = m * v.x; d[1] = m * v.y; d[2] = m * v.z; d[3] = m * v.w;
    }
    __syncthreads();

    const int jj4 = (tid & 7) * 4;
    const int rb = tid >> 3;
#pragma unroll
    for (int i = 0; i < 4; i++) {
        int rr = rb + i * 32;
        float f0 = sV[(rr - (jj4 + 0) + 31) * BSTRIDE + jj4 + 0];
        float f1 = sV[(rr - (jj4 + 1) + 31) * BSTRIDE + jj4 + 1];
        float f2 = sV[(rr - (jj4 + 2) + 31) * BSTRIDE + jj4 + 2];
        float f3 = sV[(rr - (jj4 + 3) + 31) * BSTRIDE + jj4 + 3];
        __half2 h0 = __floats2half2_rn(f0, f1);
        __half2 h1 = __floats2half2_rn(f2, f3);
        uint2 o;
        o.x = *reinterpret_cast<unsigned*>(&h0);
        o.y = *reinterpret_cast<unsigned*>(&h1);
        *(uint2*)(g_Wh + (size_t)(r0 + rr) * 4096 + j0 + jj4) = o;
    }
}

// ---------------------------------------------------------------------------
// Kernel 3: fp16 mma.sync GEMM  C[512,4096] = g_xh * g_Wh^T  (fp32 accum)
//   BM=BN=128, BK=64 fp16 elems (row = 128B -> identical swizzle/ldsm maps
//   as the proven tf32 kernel), 3-stage cp.async, 4 warps (64x64 tiles),
//   4 x m16n8k16 k-steps per chunk, intra-chunk fragment double-buffer.
// ---------------------------------------------------------------------------
#define BM 128
#define BN 128
#define BK 64
#define STAGES 3
#define NCHUNK 64                            // 4096 / 64
#define A_BYTES (BM * BK * 2)                // 16384
#define STAGE_BYTES (2 * A_BYTES)            // 32768 (A + B)
#define SMEM_TOTAL (STAGES * STAGE_BYTES)    // 98304

__global__ void __launch_bounds__(128, 1) mma_gemm_kernel(float* __restrict__ C) {
    extern __shared__ char smem[];
    const unsigned sbase = smem_u32(smem);
    const int tid = threadIdx.x;
    const int lane = tid & 31;
    const int warp = tid >> 5;
    const int m0 = blockIdx.y * BM;
    const int n0 = blockIdx.x * BN;
    const int wm = (warp & 1) * 64;
    const int wn = (warp >> 1) * 64;
    const int r = lane >> 2;
    const int c = lane & 3;
    const unsigned lane7 = lane & 7;
    const unsigned hA = lane >> 4;           // A k-half (16B) selector
    const unsigned hB = (lane >> 3) & 1;     // B k-half (16B) selector

    const __half* __restrict__ Ag = g_xh + (size_t)m0 * 4096;
    const __half* __restrict__ Bg = g_Wh + (size_t)n0 * 4096;

    // per-lane ldmatrix row-base offsets (stage-relative); rows are 128B
    unsigned aoff[4], boff[4];
#pragma unroll
    for (int mt = 0; mt < 4; mt++)
        aoff[mt] = (unsigned)((wm + mt * 16 + (lane & 15)) << 7);
#pragma unroll
    for (int np = 0; np < 4; np++)
        boff[np] = (unsigned)((wn + (2 * np + (lane >> 4)) * 8 + (lane & 7)) << 7) + A_BYTES;

    float acc[4][8][4];
#pragma unroll
    for (int mt = 0; mt < 4; mt++)
#pragma unroll
        for (int nt = 0; nt < 8; nt++)
#pragma unroll
            for (int e = 0; e < 4; e++) acc[mt][nt][e] = 0.f;

    unsigned a_f[2][4][4], b_f[2][4][4];

    // chunk cc covers k = cc*64 .. cc*64+64 (fp16 elems); row = 64 halves = 128B
#define LOAD_CHUNK(cc, stoff)                                                     \
    do {                                                                          \
        const unsigned aB = sbase + (stoff);                                      \
        const unsigned bB = aB + A_BYTES;                                         \
        const int kb = (cc) * BK;                                                 \
        _Pragma("unroll")                                                         \
        for (int i = 0; i < 8; i++) {   /* A: 128 rows x 8 16B-chunks */          \
            int idx = tid + i * 128;                                              \
            int row = idx >> 3, u = idx & 7;                                      \
            unsigned sw = (unsigned)((row << 7) + ((u ^ (row & 7)) << 4));        \
            cp_async16(aB + sw, Ag + (size_t)row * 4096 + kb + u * 8);            \
        }                                                                         \
        _Pragma("unroll")                                                         \
        for (int i = 0; i < 8; i++) {   /* B: 128 rows x 8 16B-chunks */          \
            int idx = tid + i * 128;                                              \
            int row = idx >> 3, u = idx & 7;                                      \
            unsigned sw = (unsigned)((row << 7) + ((u ^ (row & 7)) << 4));        \
            cp_async16(bB + sw, Bg + (size_t)row * 4096 + kb + u * 8);            \
        }                                                                         \
    } while (0)

    // ks in [0,4): each m16n8k16 step consumes 32B (16 halves) of the 128B row
#define LD_FRAG(buf, stoff, ks)                                                   \
    do {                                                                          \
        unsigned swA = ((2u * (ks) + hA) ^ lane7) << 4;                           \
        unsigned swB = ((2u * (ks) + hB) ^ lane7) << 4;                           \
        _Pragma("unroll")                                                         \
        for (int mt = 0; mt < 4; mt++)                                            \
            ldsm4(a_f[buf][mt], sbase + (stoff) + aoff[mt] + swA);                \
        _Pragma("unroll")                                                         \
        for (int np = 0; np < 4; np++)                                            \
            ldsm4(b_f[buf][np], sbase + (stoff) + boff[np] + swB);                \
    } while (0)

    LOAD_CHUNK(0, 0);
    asm volatile("cp.async.commit_group;" ::: "memory");
    LOAD_CHUNK(1, STAGE_BYTES);
    asm volatile("cp.async.commit_group;" ::: "memory");

    int st = 0;
    int lst = 2;
    for (int cc = 0; cc < NCHUNK; cc++) {
        asm volatile("cp.async.wait_group 1;" ::: "memory");   // chunk cc resident
        __syncthreads();

        if (cc + 2 < NCHUNK) LOAD_CHUNK(cc + 2, lst * STAGE_BYTES);
        asm volatile("cp.async.commit_group;" ::: "memory");

        const unsigned stoff = (unsigned)(st * STAGE_BYTES);
        LD_FRAG(0, stoff, 0);

#pragma unroll
        for (int ks = 0; ks < 4; ks++) {
            const int cur = ks & 1;
            if (ks < 3) LD_FRAG(cur ^ 1, stoff, ks + 1);
#pragma unroll
            for (int mt = 0; mt < 4; mt++)
#pragma unroll
                for (int nt = 0; nt < 8; nt++)
                    mma_f16(acc[mt][nt], a_f[cur][mt], &b_f[cur][nt >> 1][(nt & 1) * 2]);
        }

        st = (st + 1 == STAGES) ? 0 : st + 1;
        lst = (lst + 1 == STAGES) ? 0 : lst + 1;
    }

    // epilogue (fp32 C)
#pragma unroll
    for (int mt = 0; mt < 4; mt++) {
        int row = m0 + wm + mt * 16 + r;
#pragma unroll
        for (int nt = 0; nt < 8; nt++) {
            int col = n0 + wn + nt * 8 + 2 * c;
            *(float2*)(C + (size_t)row * 4096 + col) = make_float2(acc[mt][nt][0], acc[mt][nt][1]);
            *(float2*)(C + (size_t)(row + 8) * 4096 + col) = make_float2(acc[mt][nt][2], acc[mt][nt][3]);
        }
    }
#undef LOAD_CHUNK
#undef LD_FRAG
}

// ---------------------------------------------------------------------------
extern "C" void kernel_launch(void* const* d_in, const int* in_sizes, int n_in,
                              void* d_out, int out_size) {
    const float* x = nullptr;
    const float* V = nullptr;
    const float* alpha = nullptr;
    for (int i = 0; i < n_in; i++) {
        if (in_sizes[i] == 512 * 4096)       x     = (const float*)d_in[i];
        else if (in_sizes[i] == 4096 * 4096) V     = (const float*)d_in[i];
        else if (in_sizes[i] == 4096)        alpha = (const float*)d_in[i];
    }

    cudaFuncSetAttribute(mma_gemm_kernel, cudaFuncAttributeMaxDynamicSharedMemorySize, SMEM_TOTAL);

    dykstra_kernel<<<1, 256>>>(alpha);
    bw_rx_kernel<<<RX_BLOCKS + BW_BLOCKS, 256>>>(V, x);
    mma_gemm_kernel<<<dim3(4096 / BN, 512 / BM), 128, SMEM_TOTAL>>>((float*)d_out);
}